// round 13
// baseline (speedup 1.0000x reference)
#include <cuda_runtime.h>
#include <cstdint>

#define NWORDS  16384
#define LW      32
#define NC      64
#define E3      256
#define OUTW    770
#define GRID    444         // exactly one wave: 148 SMs * 3 blocks
#define BLOCKT  256
#define WPT     5           // words per warp tile (tiles may overlap: dup stores OK)

#define TABROW   260        // floats per char row (1040 B: 16B-aligned rows)
#define TABROWB  1040u
#define SMEM_TOTAL (NC * TABROW * 4)   // 66560 B -> 3 blocks/SM

typedef unsigned long long ull;

__device__ __forceinline__ void lds128(uint32_t a, ull &x, ull &y) {
    asm("ld.shared.v2.b64 {%0,%1}, [%2];" : "=l"(x), "=l"(y) : "r"(a));
}
__device__ __forceinline__ void fma2(ull &acc, ull c, ull b) {
    asm("fma.rn.f32x2 %0, %1, %2, %0;" : "+l"(acc) : "l"(c), "l"(b));
}
__device__ __forceinline__ ull pkf(float v) {
    ull r; uint32_t u = __float_as_uint(v);
    asm("mov.b64 %0, {%1, %1};" : "=l"(r) : "r"(u)); return r;
}

__global__ __launch_bounds__(BLOCKT, 3) void opb_kernel(
    const int* __restrict__ sntcs, const float* __restrict__ W,
    float* __restrict__ out)
{
    extern __shared__ float sTab[];          // [64][260]
    uint32_t sb;
    asm("{ .reg .u64 t; cvta.to.shared.u64 t, %1; cvt.u32.u64 %0, t; }" : "=r"(sb) : "l"(sTab));

    const int tid  = threadIdx.x;
    const int lane = tid & 31;
    const int wg   = tid >> 5;

    // ---- block word range (balanced 36/37) + warp's 5-word tile ----
    const int w0 = (int)(((long long)blockIdx.x * NWORDS) / GRID);
    const int w1 = (int)(((long long)(blockIdx.x + 1) * NWORDS) / GRID);
    const int n  = w1 - w0;
    int wsl = wg * WPT; if (wsl > n - WPT) wsl = n - WPT;   // clamp (overlap OK)
    const int ws = w0 + wsl;

    // ---- prologue: char loads for the tile (issue before fill) ----
    int ch[WPT];
    #pragma unroll
    for (int t = 0; t < WPT; t++)
        ch[t] = sntcs[(size_t)(ws + t) * LW + lane];

    // ---- fill fp32 table: thread = (char, dim-quarter); CF (phase-split) ----
    {
        const int fc = tid & 63;
        const int fq = tid >> 6;
        #pragma unroll
        for (int i = 0; i < 16; i++) {
            const int d0 = fq * 64 + i * 4;
            float4 v;
            v.x = W[(d0 + 0) * NC + fc];
            v.y = W[(d0 + 1) * NC + fc];
            v.z = W[(d0 + 2) * NC + fc];
            v.w = W[(d0 + 3) * NC + fc];
            *(float4*)(sTab + fc * TABROW + d0) = v;
        }
    }

    // ---- metadata: all register-resident (no smem, no block sync) ----
    float cl[WPT], chh[WPT];        // counts of char==lane / char==lane+32
    int   fcv[WPT], env[WPT];       // first char, ends char
    #pragma unroll
    for (int t = 0; t < WPT; t++) {
        int c = ch[t];
        unsigned key = ((unsigned)c << 5) | (unsigned)(31 - lane);
        #pragma unroll
        for (int off = 16; off; off >>= 1) {
            unsigned o = __shfl_xor_sync(0xffffffffu, key, off);
            key = key > o ? key : o;
        }
        int p  = 31 - (int)(key & 31u);                 // first-occurrence argmax
        int wl = p - 1; if (wl < 0) wl = 0;             // relu(argmax-1)
        int ends = __shfl_sync(0xffffffffu, c, wl);     // gather BEFORE scatter
        int s = (lane == wl) ? 0 : c;                   // scatter 0 at wl
        if (lane == 31) s = ends;                       // last := ends
        fcv[t] = __shfl_sync(0xffffffffu, s, 0);        // first char (post-edit)
        env[t] = ends;
        int c0 = 0, c1 = 0;                             // counts, interior 1..30
        #pragma unroll
        for (int l = 1; l <= 30; l++) {
            int sl = __shfl_sync(0xffffffffu, s, l);
            c0 += (sl == lane);
            c1 += (sl == lane + 32);
        }
        cl[t]  = (float)c0;
        chh[t] = (float)c1;
    }
    __syncthreads();                 // table ready (the only block barrier)

    // ---- GEMM: bow[w][d] = sum_c cnt[w][c] * Wt[c][d]; counts via shuffle ----
    ull acc[WPT][4];
    #pragma unroll
    for (int t = 0; t < WPT; t++)
        #pragma unroll
        for (int j = 0; j < 4; j++) acc[t][j] = 0ull;

    const uint32_t tb = sb + (uint32_t)lane * 16u;
    #pragma unroll 4
    for (int k = 0; k < 32; k++) {                      // chars 0..31
        ull b0, b1, b2, b3;
        lds128(tb + (uint32_t)k * TABROWB,        b0, b1);
        lds128(tb + (uint32_t)k * TABROWB + 512u, b2, b3);
        #pragma unroll
        for (int t = 0; t < WPT; t++) {
            ull p = pkf(__shfl_sync(0xffffffffu, cl[t], k));
            fma2(acc[t][0], p, b0); fma2(acc[t][1], p, b1);
            fma2(acc[t][2], p, b2); fma2(acc[t][3], p, b3);
        }
    }
    #pragma unroll 4
    for (int k = 0; k < 32; k++) {                      // chars 32..63
        ull b0, b1, b2, b3;
        lds128(tb + (uint32_t)(k + 32) * TABROWB,        b0, b1);
        lds128(tb + (uint32_t)(k + 32) * TABROWB + 512u, b2, b3);
        #pragma unroll
        for (int t = 0; t < WPT; t++) {
            ull p = pkf(__shfl_sync(0xffffffffu, chh[t], k));
            fma2(acc[t][0], p, b0); fma2(acc[t][1], p, b1);
            fma2(acc[t][2], p, b2); fma2(acc[t][3], p, b3);
        }
    }

    // ---- epilogue: bow stores + first/last gathers + pad ----
    #pragma unroll
    for (int t = 0; t < WPT; t++) {
        const int gw = ws + t;
        float* o = out + (size_t)gw * OUTW;
        const int d4 = lane * 4;
        *(ull*)(o + 258 + d4)       = acc[t][0];        // bow (base 2+E3=258)
        *(ull*)(o + 260 + d4)       = acc[t][1];
        *(ull*)(o + 258 + 128 + d4) = acc[t][2];
        *(ull*)(o + 260 + 128 + d4) = acc[t][3];
        const uint32_t fo = (uint32_t)fcv[t] * TABROWB;
        const uint32_t lo = (uint32_t)env[t] * TABROWB;
        const uint32_t la = (uint32_t)lane * 16u;
        ull x, y;
        lds128(sb + fo + la, x, y);                     // first
        *(ull*)(o + 2 + d4)   = x;  *(ull*)(o + 4 + d4)   = y;
        lds128(sb + fo + 512u + la, x, y);
        *(ull*)(o + 130 + d4) = x;  *(ull*)(o + 132 + d4) = y;
        lds128(sb + lo + la, x, y);                     // last
        *(ull*)(o + 514 + d4) = x;  *(ull*)(o + 516 + d4) = y;
        lds128(sb + lo + 512u + la, x, y);
        *(ull*)(o + 642 + d4) = x;  *(ull*)(o + 644 + d4) = y;
        if (lane == 0) *(ull*)o = 0ull;                 // left zero pad
    }
}

extern "C" void kernel_launch(void* const* d_in, const int* in_sizes, int n_in,
                              void* d_out, int out_size)
{
    const int*   sntcs = (const int*)d_in[0];
    const float* W     = (const float*)d_in[1];
    float*       out   = (float*)d_out;

    cudaFuncSetAttribute(opb_kernel, cudaFuncAttributeMaxDynamicSharedMemorySize, SMEM_TOTAL);
    opb_kernel<<<GRID, BLOCKT, SMEM_TOTAL>>>(sntcs, W, out);
}

// round 14
// speedup vs baseline: 1.0579x; 1.0579x over previous
#include <cuda_runtime.h>
#include <cstdint>

#define NWORDS  16384
#define LW      32
#define NC      64
#define E3      256
#define OUTW    770
#define GRID    444         // exactly one wave: 148 SMs * 3 blocks
#define BLOCKT  256
#define WPT     5           // words per warp tile (tiles may overlap: dup work OK)

#define TABROW   260        // floats per char row (1040 B: 16B-aligned rows)
#define TABROWB  1040u
#define CNTROW   40         // floats per count row (160 B)
#define TAB_OFF  0
#define CNT_OFF  66560      // counts [64][40] f32 = 10240 B
#define SMEM_TOTAL 76800    // 3 blocks/SM: 230400 <= 233472

typedef unsigned long long ull;

__device__ __forceinline__ void lds128(uint32_t a, ull &x, ull &y) {
    asm("ld.shared.v2.b64 {%0,%1}, [%2];" : "=l"(x), "=l"(y) : "r"(a));
}
__device__ __forceinline__ void fma2(ull &acc, ull c, ull b) {
    asm("fma.rn.f32x2 %0, %1, %2, %0;" : "+l"(acc) : "l"(c), "l"(b));
}
__device__ __forceinline__ ull pkf(float v) {
    ull r; uint32_t u = __float_as_uint(v);
    asm("mov.b64 %0, {%1, %1};" : "=l"(r) : "r"(u)); return r;
}

__global__ __launch_bounds__(BLOCKT, 3) void opb_kernel(
    const int* __restrict__ sntcs, const float* __restrict__ W,
    float* __restrict__ out)
{
    extern __shared__ float smem[];
    float* sTab = smem;                       // [64][260]
    float* sCnt = smem + CNT_OFF / 4;         // [64][40]
    uint32_t sb;
    asm("{ .reg .u64 t; cvta.to.shared.u64 t, %1; cvt.u32.u64 %0, t; }" : "=r"(sb) : "l"(smem));

    const int tid  = threadIdx.x;
    const int lane = tid & 31;
    const int wg   = tid >> 5;

    // ---- block word range (balanced 36/37) + warp's 5-word tile ----
    const int w0 = (int)(((long long)blockIdx.x * NWORDS) / GRID);
    const int w1 = (int)(((long long)(blockIdx.x + 1) * NWORDS) / GRID);
    const int n  = w1 - w0;
    int wsl = wg * WPT; if (wsl > n - WPT) wsl = n - WPT;   // clamp (overlap OK)
    const int ws = w0 + wsl;

    // ---- prologue: char loads for the tile (issue before fill) ----
    int ch[WPT];
    #pragma unroll
    for (int t = 0; t < WPT; t++)
        ch[t] = sntcs[(size_t)(ws + t) * LW + lane];

    // ---- fill fp32 table: thread = (char, dim-quarter); conflict-free ----
    {
        const int fc = tid & 63;
        const int fq = tid >> 6;
        #pragma unroll
        for (int i = 0; i < 16; i++) {
            const int d0 = fq * 64 + i * 4;
            float4 v;
            v.x = W[(d0 + 0) * NC + fc];
            v.y = W[(d0 + 1) * NC + fc];
            v.z = W[(d0 + 2) * NC + fc];
            v.w = W[(d0 + 3) * NC + fc];
            *(float4*)(sTab + fc * TABROW + d0) = v;
        }
    }
    // ---- zero counts table ----
    for (int i = tid; i < NC * CNTROW; i += BLOCKT) sCnt[i] = 0.0f;
    __syncthreads();                          // counts zeroed (table fill also done)

    // ---- metadata: argmax/edit + match-based counts -> smem ----
    int fcv[WPT], env[WPT];
    #pragma unroll
    for (int t = 0; t < WPT; t++) {
        int c = ch[t];
        unsigned key = ((unsigned)c << 5) | (unsigned)(31 - lane);
        #pragma unroll
        for (int off = 16; off; off >>= 1) {
            unsigned o = __shfl_xor_sync(0xffffffffu, key, off);
            key = key > o ? key : o;
        }
        int p  = 31 - (int)(key & 31u);                 // first-occurrence argmax
        int wl = p - 1; if (wl < 0) wl = 0;             // relu(argmax-1)
        int ends = __shfl_sync(0xffffffffu, c, wl);     // gather BEFORE scatter
        int s = (lane == wl) ? 0 : c;                   // scatter 0 at wl
        if (lane == 31) s = ends;                       // last := ends
        fcv[t] = __shfl_sync(0xffffffffu, s, 0);        // first char (post-edit)
        env[t] = ends;
        // counts over interior lanes 1..30 via match+popc; group leader stores
        unsigned m = __match_any_sync(0xffffffffu, s);
        int cnt = __popc(m & 0x7FFFFFFEu);
        if ((m & ((1u << lane) - 1u)) == 0u)            // lowest lane of group
            sCnt[s * CNTROW + wsl + t] = (float)cnt;
    }
    __syncthreads();                          // counts ready

    // ---- GEMM: bow[w][d] = sum_c cnt[w][c] * Wt[c][d]  (f32x2) ----
    ull acc[WPT][4];
    #pragma unroll
    for (int t = 0; t < WPT; t++)
        #pragma unroll
        for (int j = 0; j < 4; j++) acc[t][j] = 0ull;

    const uint32_t tb = sb + (uint32_t)lane * 16u;
    const float* cw = sCnt + wsl;             // counts for this warp's words
    #pragma unroll 4
    for (int k = 0; k < NC; k++) {
        ull b0, b1, b2, b3;
        lds128(tb + (uint32_t)k * TABROWB,        b0, b1);   // dims 4l..4l+3
        lds128(tb + (uint32_t)k * TABROWB + 512u, b2, b3);   // dims 128+4l..
        const float* ck = cw + k * CNTROW;
        ull p0 = pkf(ck[0]), p1 = pkf(ck[1]), p2 = pkf(ck[2]),
            p3 = pkf(ck[3]), p4 = pkf(ck[4]);
        fma2(acc[0][0], p0, b0); fma2(acc[0][1], p0, b1);
        fma2(acc[0][2], p0, b2); fma2(acc[0][3], p0, b3);
        fma2(acc[1][0], p1, b0); fma2(acc[1][1], p1, b1);
        fma2(acc[1][2], p1, b2); fma2(acc[1][3], p1, b3);
        fma2(acc[2][0], p2, b0); fma2(acc[2][1], p2, b1);
        fma2(acc[2][2], p2, b2); fma2(acc[2][3], p2, b3);
        fma2(acc[3][0], p3, b0); fma2(acc[3][1], p3, b1);
        fma2(acc[3][2], p3, b2); fma2(acc[3][3], p3, b3);
        fma2(acc[4][0], p4, b0); fma2(acc[4][1], p4, b1);
        fma2(acc[4][2], p4, b2); fma2(acc[4][3], p4, b3);
    }

    // ---- epilogue: bow stores + first/last gathers + pad ----
    #pragma unroll
    for (int t = 0; t < WPT; t++) {
        const int gw = ws + t;
        float* o = out + (size_t)gw * OUTW;
        const int d4 = lane * 4;
        *(ull*)(o + 258 + d4)       = acc[t][0];        // bow (base 2+E3=258)
        *(ull*)(o + 260 + d4)       = acc[t][1];
        *(ull*)(o + 258 + 128 + d4) = acc[t][2];
        *(ull*)(o + 260 + 128 + d4) = acc[t][3];
        const uint32_t fo = (uint32_t)fcv[t] * TABROWB;
        const uint32_t lo = (uint32_t)env[t] * TABROWB;
        const uint32_t la = (uint32_t)lane * 16u;
        ull x, y;
        lds128(sb + fo + la, x, y);                     // first
        *(ull*)(o + 2 + d4)   = x;  *(ull*)(o + 4 + d4)   = y;
        lds128(sb + fo + 512u + la, x, y);
        *(ull*)(o + 130 + d4) = x;  *(ull*)(o + 132 + d4) = y;
        lds128(sb + lo + la, x, y);                     // last
        *(ull*)(o + 514 + d4) = x;  *(ull*)(o + 516 + d4) = y;
        lds128(sb + lo + 512u + la, x, y);
        *(ull*)(o + 642 + d4) = x;  *(ull*)(o + 644 + d4) = y;
        if (lane == 0) *(ull*)o = 0ull;                 // left zero pad
    }
}

extern "C" void kernel_launch(void* const* d_in, const int* in_sizes, int n_in,
                              void* d_out, int out_size)
{
    const int*   sntcs = (const int*)d_in[0];
    const float* W     = (const float*)d_in[1];
    float*       out   = (float*)d_out;

    cudaFuncSetAttribute(opb_kernel, cudaFuncAttributeMaxDynamicSharedMemorySize, SMEM_TOTAL);
    opb_kernel<<<GRID, BLOCKT, SMEM_TOTAL>>>(sntcs, W, out);
}

// round 15
// speedup vs baseline: 1.1204x; 1.0591x over previous
#include <cuda_runtime.h>
#include <cstdint>

#define NWORDS  16384
#define LW      32
#define NC      64
#define E3      256
#define OUTW    770
#define HBLKS   296         // blocks per dim-half
#define GRID    592         // one wave: 148 SMs * 4 blocks
#define BLOCKT  256
#define WPT     7           // words per warp (tiles may overlap; dup work OK)

#define TROW    132         // floats per char row (528 B, 16B-aligned)
#define TROWB   528u
#define TAB_OFF 0           // half table [64][132] = 33792 B
#define CNT_OFF 33792       // counts [8 warps][64 k][8 f32] = 16384 B
#define SMEM_TOTAL 50176    // 4 blocks/SM: 200704 <= 233472

typedef unsigned long long ull;

__device__ __forceinline__ void lds128(uint32_t a, ull &x, ull &y) {
    asm("ld.shared.v2.b64 {%0,%1}, [%2];" : "=l"(x), "=l"(y) : "r"(a));
}
__device__ __forceinline__ void fma2(ull &acc, ull c, ull b) {
    asm("fma.rn.f32x2 %0, %1, %2, %0;" : "+l"(acc) : "l"(c), "l"(b));
}
__device__ __forceinline__ ull pkf(float v) {
    ull r; uint32_t u = __float_as_uint(v);
    asm("mov.b64 %0, {%1, %1};" : "=l"(r) : "r"(u)); return r;
}

__global__ __launch_bounds__(BLOCKT, 4) void opb_kernel(
    const int* __restrict__ sntcs, const float* __restrict__ W,
    float* __restrict__ out)
{
    extern __shared__ float smem[];
    uint32_t sb;
    asm("{ .reg .u64 t; cvta.to.shared.u64 t, %1; cvt.u32.u64 %0, t; }" : "=r"(sb) : "l"(smem));

    const int tid  = threadIdx.x;
    const int lane = tid & 31;
    const int wg   = tid >> 5;
    const int h    = (blockIdx.x >= HBLKS);     // dim-half owned by this block
    const int hb   = blockIdx.x - (h ? HBLKS : 0);

    // ---- word range (balanced 55/56) + warp's 7-word tile ----
    const int w0 = (int)(((long long)hb * NWORDS) / HBLKS);
    const int w1 = (int)(((long long)(hb + 1) * NWORDS) / HBLKS);
    const int n  = w1 - w0;
    int wsl = wg * WPT; if (wsl > n - WPT) wsl = n - WPT;   // clamp (overlap OK)
    const int ws = w0 + wsl;

    // ---- prologue: char loads (issued before fill) ----
    int ch[WPT];
    #pragma unroll
    for (int t = 0; t < WPT; t++)
        ch[t] = sntcs[(size_t)(ws + t) * LW + lane];

    // ---- fill half-table: thread = (char, 32-dim quarter) ----
    {
        const int fc = tid & 63;
        const int fq = tid >> 6;
        #pragma unroll
        for (int i = 0; i < 8; i++) {
            const int d0 = fq * 32 + i * 4;
            float4 v;
            v.x = W[(h * 128 + d0 + 0) * NC + fc];
            v.y = W[(h * 128 + d0 + 1) * NC + fc];
            v.z = W[(h * 128 + d0 + 2) * NC + fc];
            v.w = W[(h * 128 + d0 + 3) * NC + fc];
            *(float4*)(smem + fc * TROW + d0) = v;
        }
    }

    // ---- zero this warp's count region [64 k][8 f32] ----
    {
        float* cz = smem + CNT_OFF / 4 + wg * 512;
        #pragma unroll
        for (int i = 0; i < 16; i++) cz[lane + i * 32] = 0.0f;
    }
    __syncwarp();

    // ---- metadata: argmax/edit + match counts -> warp-private smem ----
    uint32_t mo[WPT];                           // packed (first|last) row offsets
    #pragma unroll
    for (int t = 0; t < WPT; t++) {
        int c = ch[t];
        unsigned key = ((unsigned)c << 5) | (unsigned)(31 - lane);
        #pragma unroll
        for (int off = 16; off; off >>= 1) {
            unsigned o = __shfl_xor_sync(0xffffffffu, key, off);
            key = key > o ? key : o;
        }
        int p  = 31 - (int)(key & 31u);                 // first-occurrence argmax
        int wl = p - 1; if (wl < 0) wl = 0;             // relu(argmax-1)
        int ends = __shfl_sync(0xffffffffu, c, wl);     // gather BEFORE scatter
        int s = (lane == wl) ? 0 : c;                   // scatter 0 at wl
        if (lane == 31) s = ends;                       // last := ends
        int fc2 = __shfl_sync(0xffffffffu, s, 0);       // first char (post-edit)
        mo[t] = ((uint32_t)fc2 * TROWB) | (((uint32_t)ends * TROWB) << 16);
        unsigned m = __match_any_sync(0xffffffffu, s);  // counts, interior 1..30
        int cnt = __popc(m & 0x7FFFFFFEu);
        if ((m & ((1u << lane) - 1u)) == 0u)            // group leader stores
            smem[CNT_OFF / 4 + wg * 512 + s * 8 + t] = (float)cnt;
    }
    __syncthreads();        // table + counts ready (only block barrier)

    // ---- GEMM: bow[w][d] = sum_c cnt[w][c] * Wt[c][d], half dims ----
    ull acc[WPT][2];
    #pragma unroll
    for (int t = 0; t < WPT; t++) { acc[t][0] = 0ull; acc[t][1] = 0ull; }

    const uint32_t tb = sb + (uint32_t)lane * 16u;
    const uint32_t cb = sb + CNT_OFF + (uint32_t)wg * 2048u;
    #pragma unroll 4
    for (int k = 0; k < NC; k++) {
        ull b0, b1, q0, q1, q2, q3;
        lds128(tb + (uint32_t)k * TROWB, b0, b1);      // dims 4l..4l+3 (4 wf)
        lds128(cb + (uint32_t)k * 32u,        q0, q1); // counts w0..3 (broadcast)
        lds128(cb + (uint32_t)k * 32u + 16u,  q2, q3); // counts w4..7 (broadcast)
        float c0,c1,c2,c3,c4,c5,c6,c7;
        asm("mov.b64 {%0,%1}, %2;" : "=f"(c0), "=f"(c1) : "l"(q0));
        asm("mov.b64 {%0,%1}, %2;" : "=f"(c2), "=f"(c3) : "l"(q1));
        asm("mov.b64 {%0,%1}, %2;" : "=f"(c4), "=f"(c5) : "l"(q2));
        asm("mov.b64 {%0,%1}, %2;" : "=f"(c6), "=f"(c7) : "l"(q3));
        ull p;
        p = pkf(c0); fma2(acc[0][0], p, b0); fma2(acc[0][1], p, b1);
        p = pkf(c1); fma2(acc[1][0], p, b0); fma2(acc[1][1], p, b1);
        p = pkf(c2); fma2(acc[2][0], p, b0); fma2(acc[2][1], p, b1);
        p = pkf(c3); fma2(acc[3][0], p, b0); fma2(acc[3][1], p, b1);
        p = pkf(c4); fma2(acc[4][0], p, b0); fma2(acc[4][1], p, b1);
        p = pkf(c5); fma2(acc[5][0], p, b0); fma2(acc[5][1], p, b1);
        p = pkf(c6); fma2(acc[6][0], p, b0); fma2(acc[6][1], p, b1);
    }

    // ---- epilogue: bow stores + first/last gathers + pad ----
    const int col = h * 128 + lane * 4;
    #pragma unroll
    for (int t = 0; t < WPT; t++) {
        float* o = out + (size_t)(ws + t) * OUTW;
        *(ull*)(o + 258 + col) = acc[t][0];             // bow (base 2+E3=258)
        *(ull*)(o + 260 + col) = acc[t][1];
        const uint32_t fo = mo[t] & 0xFFFFu;
        const uint32_t lo = mo[t] >> 16;
        ull x, y;
        lds128(sb + fo + (uint32_t)lane * 16u, x, y);   // first
        *(ull*)(o + 2 + col)   = x;  *(ull*)(o + 4 + col)   = y;
        lds128(sb + lo + (uint32_t)lane * 16u, x, y);   // last
        *(ull*)(o + 514 + col) = x;  *(ull*)(o + 516 + col) = y;
        if (h == 0 && lane == 0) *(ull*)o = 0ull;       // left zero pad
    }
}

extern "C" void kernel_launch(void* const* d_in, const int* in_sizes, int n_in,
                              void* d_out, int out_size)
{
    const int*   sntcs = (const int*)d_in[0];
    const float* W     = (const float*)d_in[1];
    float*       out   = (float*)d_out;

    cudaFuncSetAttribute(opb_kernel, cudaFuncAttributeMaxDynamicSharedMemorySize, SMEM_TOTAL);
    opb_kernel<<<GRID, BLOCKT, SMEM_TOTAL>>>(sntcs, W, out);
}

// round 17
// speedup vs baseline: 1.2293x; 1.0972x over previous
#include <cuda_runtime.h>
#include <cuda_bf16.h>
#include <cstdint>

#define NWORDS  16384
#define LW      32
#define NC      64
#define OUTW    770
#define GRID    296          // one wave: 148 SMs * 2 blocks
#define BLOCKT  512
#define SLOTS   64

#define KPROWB  148          // bytes per dim-row of WP tables (37 u32 char-pairs)
#define CROWB   144          // bytes per slot-row of counts (72 bf16)
#define WPHI_OFF 0           // [256][37] u32 = 37888 B
#define WPLO_OFF 37888
#define CNT_OFF  75776       // [64][72] bf16 = 9216 B
#define META_OFF 84992       // [64] u32
#define SMEM_TOTAL 85248

__device__ __forceinline__ void mma_bf16(float &d0, float &d1, float &d2, float &d3,
    uint32_t a0, uint32_t a1, uint32_t a2, uint32_t a3, uint32_t b0, uint32_t b1)
{
    asm volatile(
        "mma.sync.aligned.m16n8k16.row.col.f32.bf16.bf16.f32 "
        "{%0,%1,%2,%3}, {%4,%5,%6,%7}, {%8,%9}, {%0,%1,%2,%3};"
        : "+f"(d0), "+f"(d1), "+f"(d2), "+f"(d3)
        : "r"(a0), "r"(a1), "r"(a2), "r"(a3), "r"(b0), "r"(b1));
}
__device__ __forceinline__ float bf_lo(uint32_t v) { return __uint_as_float(v << 16); }
__device__ __forceinline__ float bf_hi(uint32_t v) { return __uint_as_float(v & 0xFFFF0000u); }

__global__ __launch_bounds__(BLOCKT, 2) void opb_kernel(
    const int* __restrict__ sntcs, const float* __restrict__ W,
    float* __restrict__ out)
{
    extern __shared__ char smem[];
    uint32_t* sMeta = (uint32_t*)(smem + META_OFF);

    const int tid  = threadIdx.x;
    const int lane = tid & 31;
    const int wg   = tid >> 5;                  // 16 warps

    const int w0 = (int)(((long long)blockIdx.x * NWORDS) / GRID);
    const int w1 = (int)(((long long)(blockIdx.x + 1) * NWORDS) / GRID);
    const int n  = w1 - w0;                     // 55 or 56 words

    // ---- meta prologue: chars for this warp's 4 slots (slot>=n dups last word) ----
    int ch[4];
    #pragma unroll
    for (int t = 0; t < 4; t++) {
        int s = wg * 4 + t;
        int w = w0 + (s < n ? s : n - 1);
        ch[t] = sntcs[(size_t)w * LW + lane];
    }

    // ---- fill WP tables: WP[d][kp] = {bf16 W[2kp][d] lo, bf16 W[2kp+1][d] hi} ----
    {
        const int c  = tid & 63;                // char (lane-consecutive: coalesced LDG)
        const int dc = tid >> 6;                // dim chunk 0..7
        const bool ev = (lane & 1) == 0;
        const int kpo = (c >> 1) * 4;
        #pragma unroll 4
        for (int i = 0; i < 32; i++) {
            const int d = dc * 32 + i;
            float w  = W[d * NC + c];
            float wR = __shfl_xor_sync(0xffffffffu, w, 1);
            if (ev) {                           // even char owns pair (c, c+1)
                __nv_bfloat16 hL = __float2bfloat16(w);
                __nv_bfloat16 hR = __float2bfloat16(wR);
                __nv_bfloat16 lL = __float2bfloat16(w  - __bfloat162float(hL));
                __nv_bfloat16 lR = __float2bfloat16(wR - __bfloat162float(hR));
                uint32_t hp = ((uint32_t)__bfloat16_as_ushort(hR) << 16) | __bfloat16_as_ushort(hL);
                uint32_t lp = ((uint32_t)__bfloat16_as_ushort(lR) << 16) | __bfloat16_as_ushort(lL);
                *(uint32_t*)(smem + WPHI_OFF + d * KPROWB + kpo) = hp;
                *(uint32_t*)(smem + WPLO_OFF + d * KPROWB + kpo) = lp;
            }
        }
    }

    // ---- zero this warp's 4 count rows (contiguous 576 B) ----
    {
        uint32_t* z = (uint32_t*)(smem + CNT_OFF + wg * 4 * CROWB);
        #pragma unroll
        for (int k2 = 0; k2 < 5; k2++) {
            int idx = k2 * 32 + lane;
            if (idx < 144) z[idx] = 0u;
        }
    }
    __syncwarp();

    // ---- metadata per slot: argmax/edit + match counts (bf16) ----
    #pragma unroll
    for (int t = 0; t < 4; t++) {
        const int s = wg * 4 + t;
        int c = ch[t];
        unsigned key = ((unsigned)c << 5) | (unsigned)(31 - lane);
        #pragma unroll
        for (int off = 16; off; off >>= 1) {
            unsigned o = __shfl_xor_sync(0xffffffffu, key, off);
            key = key > o ? key : o;
        }
        int p  = 31 - (int)(key & 31u);                 // first-occurrence argmax
        int wl = p - 1; if (wl < 0) wl = 0;             // relu(argmax-1)
        int ends = __shfl_sync(0xffffffffu, c, wl);     // gather BEFORE scatter
        int sv = (lane == wl) ? 0 : c;                  // scatter 0 at wl
        if (lane == 31) sv = ends;                      // last := ends
        int fc2 = __shfl_sync(0xffffffffu, sv, 0);      // first char (post-edit)
        unsigned m = __match_any_sync(0xffffffffu, sv); // counts, interior 1..30
        int cnt = __popc(m & 0x7FFFFFFEu);
        if ((m & ((1u << lane) - 1u)) == 0u) {          // group leader stores
            uint16_t cv = __bfloat16_as_ushort(__float2bfloat16((float)cnt));
            *(uint16_t*)(smem + CNT_OFF + s * CROWB + sv * 2) = cv;
        }
        if (lane == 0)
            sMeta[s] = (uint32_t)fc2 | ((uint32_t)ends << 16);
    }
    __syncthreads();    // tables + counts ready (only block barrier)

    // ---- tensor GEMM: D[16 words x 64 dims] per warp, K=64 chars ----
    const int gp  = wg >> 2;            // word group 0..3 (16 slots each)
    const int nw  = wg & 3;             // dim quarter
    const int g   = lane >> 2;          // fragment groupID
    const int t4  = lane & 3;           // threadID in group
    const int sB  = gp * 16;
    const int nb0 = nw * 64;

    float D[8][4];
    #pragma unroll
    for (int j = 0; j < 8; j++)
        { D[j][0] = 0.f; D[j][1] = 0.f; D[j][2] = 0.f; D[j][3] = 0.f; }

    const char* aA  = smem + CNT_OFF + (sB + g) * CROWB + t4 * 4;
    const char* aBh = smem + WPHI_OFF + (nb0 + g) * KPROWB + t4 * 4;
    const char* aBl = smem + WPLO_OFF + (nb0 + g) * KPROWB + t4 * 4;

    #pragma unroll
    for (int ks = 0; ks < 4; ks++) {
        // A frag (m16n8k16): a0 = [row g][k 16ks+2t4..+1], a1 = row+8,
        //                    a2 = [row g][k +8 -> +16 B], a3 = row+8, k+8
        uint32_t a0 = *(const uint32_t*)(aA + ks * 32);
        uint32_t a1 = *(const uint32_t*)(aA + ks * 32 + 8 * CROWB);
        uint32_t a2 = *(const uint32_t*)(aA + ks * 32 + 16);
        uint32_t a3 = *(const uint32_t*)(aA + ks * 32 + 8 * CROWB + 16);
        #pragma unroll
        for (int j = 0; j < 8; j++) {
            const int bo = j * 8 * KPROWB + ks * 32;
            uint32_t bh0 = *(const uint32_t*)(aBh + bo);
            uint32_t bh1 = *(const uint32_t*)(aBh + bo + 16);
            mma_bf16(D[j][0], D[j][1], D[j][2], D[j][3], a0, a1, a2, a3, bh0, bh1);
            uint32_t bl0 = *(const uint32_t*)(aBl + bo);
            uint32_t bl1 = *(const uint32_t*)(aBl + bo + 16);
            mma_bf16(D[j][0], D[j][1], D[j][2], D[j][3], a0, a1, a2, a3, bl0, bl1);
        }
    }

    // ---- D stores: bow segment (258..513) ----
    {
        const int slo = sB + g, shi = sB + g + 8;
        const int wlo = w0 + (slo < n ? slo : n - 1);
        const int whi = w0 + (shi < n ? shi : n - 1);
        #pragma unroll
        for (int j = 0; j < 8; j++) {
            const int dcol = 258 + nb0 + 8 * j + 2 * t4;
            *(float2*)(out + (size_t)wlo * OUTW + dcol) = make_float2(D[j][0], D[j][1]);
            *(float2*)(out + (size_t)whi * OUTW + dcol) = make_float2(D[j][2], D[j][3]);
        }
    }

    // ---- first/last + pad for this warp's 4 slots (hi+lo reconstruction) ----
    #pragma unroll
    for (int t = 0; t < 4; t++) {
        const int s = wg * 4 + t;
        const int w = w0 + (s < n ? s : n - 1);
        const uint32_t me = sMeta[s];
        const int fc = (int)(me & 0xFFFFu), en = (int)(me >> 16);
        float* o = out + (size_t)w * OUTW;
        #pragma unroll
        for (int j = 0; j < 8; j++) {
            const int d = j * 32 + lane;                // banks 5*lane: CF
            const char* ad = smem + d * KPROWB;
            uint32_t hf = *(const uint32_t*)(ad + WPHI_OFF + (fc >> 1) * 4);
            uint32_t lf = *(const uint32_t*)(ad + WPLO_OFF + (fc >> 1) * 4);
            o[2 + d] = (fc & 1) ? (bf_hi(hf) + bf_hi(lf)) : (bf_lo(hf) + bf_lo(lf));
            uint32_t he = *(const uint32_t*)(ad + WPHI_OFF + (en >> 1) * 4);
            uint32_t le = *(const uint32_t*)(ad + WPLO_OFF + (en >> 1) * 4);
            o[514 + d] = (en & 1) ? (bf_hi(he) + bf_hi(le)) : (bf_lo(he) + bf_lo(le));
        }
        if (lane == 0) *(float2*)o = make_float2(0.f, 0.f);   // left zero pad
    }
}

extern "C" void kernel_launch(void* const* d_in, const int* in_sizes, int n_in,
                              void* d_out, int out_size)
{
    const int*   sntcs = (const int*)d_in[0];
    const float* W     = (const float*)d_in[1];
    float*       out   = (float*)d_out;

    cudaFuncSetAttribute(opb_kernel, cudaFuncAttributeMaxDynamicSharedMemorySize, SMEM_TOTAL);
    opb_kernel<<<GRID, BLOCKT, SMEM_TOTAL>>>(sntcs, W, out);
}